// round 3
// baseline (speedup 1.0000x reference)
#include <cuda_runtime.h>

#define Hdim 64
#define Nn   100000
#define Ee   1000000
#define Gg   64

// ---------------- scratch (static device arrays: no allocation) ----------------
__device__ float g_aggsum[Nn * Hdim];
__device__ float g_aggcnt[Nn];
__device__ float g_gsum[Gg * Hdim];
__device__ float g_gcnt[Gg];

// ---------------- helpers ----------------
__device__ __forceinline__ float gelu_f(float v) {
    return 0.5f * v * (1.0f + erff(v * 0.7071067811865476f));
}

__device__ __forceinline__ void zero4(float (&a)[4][4]) {
#pragma unroll
    for (int i = 0; i < 4; ++i)
#pragma unroll
        for (int j = 0; j < 4; ++j) a[i][j] = 0.0f;
}

__device__ __forceinline__ void cp_smem(float* dst, const float* src, int nfloats, int tid) {
    const float4* s4 = (const float4*)src;
    float4* d4 = (float4*)dst;
    for (int i = tid; i < (nfloats >> 2); i += 256) d4[i] = s4[i];
}

// type-A GEMM: X k-major in smem, stride 68 floats, e-index XOR-swizzled by ((k>>6)&3)<<3
template <int K, int KB>
__device__ __forceinline__ void gemmA(const float* __restrict__ Xs, const float* __restrict__ Ws,
                                      int i4, int j4, float (&a)[4][4]) {
#pragma unroll 4
    for (int k = 0; k < K; ++k) {
        int kk = KB + k;
        float4 xv = *(const float4*)(Xs + kk * 68 + (i4 ^ (((kk >> 6) & 3) << 3)));
        float4 wv = *(const float4*)(Ws + k * 64 + j4);
        a[0][0] += xv.x * wv.x; a[0][1] += xv.x * wv.y; a[0][2] += xv.x * wv.z; a[0][3] += xv.x * wv.w;
        a[1][0] += xv.y * wv.x; a[1][1] += xv.y * wv.y; a[1][2] += xv.y * wv.z; a[1][3] += xv.y * wv.w;
        a[2][0] += xv.z * wv.x; a[2][1] += xv.z * wv.y; a[2][2] += xv.z * wv.z; a[2][3] += xv.z * wv.w;
        a[3][0] += xv.w * wv.x; a[3][1] += xv.w * wv.y; a[3][2] += xv.w * wv.z; a[3][3] += xv.w * wv.w;
    }
}

// type-B GEMM: H row-major in smem (stride 68), scalar broadcast reads
template <int K>
__device__ __forceinline__ void gemmB(const float* __restrict__ Hs, const float* __restrict__ Ws,
                                      int i4, int j4, float (&a)[4][4]) {
#pragma unroll 4
    for (int k = 0; k < K; ++k) {
        float4 wv = *(const float4*)(Ws + k * 64 + j4);
        float x0 = Hs[(i4 + 0) * 68 + k];
        float x1 = Hs[(i4 + 1) * 68 + k];
        float x2 = Hs[(i4 + 2) * 68 + k];
        float x3 = Hs[(i4 + 3) * 68 + k];
        a[0][0] += x0 * wv.x; a[0][1] += x0 * wv.y; a[0][2] += x0 * wv.z; a[0][3] += x0 * wv.w;
        a[1][0] += x1 * wv.x; a[1][1] += x1 * wv.y; a[1][2] += x1 * wv.z; a[1][3] += x1 * wv.w;
        a[2][0] += x2 * wv.x; a[2][1] += x2 * wv.y; a[2][2] += x2 * wv.z; a[2][3] += x2 * wv.w;
        a[3][0] += x3 * wv.x; a[3][1] += x3 * wv.y; a[3][2] += x3 * wv.z; a[3][3] += x3 * wv.w;
    }
}

// bias + exact GELU, store row-major into H (stride 68)
__device__ __forceinline__ void storeH(float* __restrict__ Hs, int i4, int j4,
                                       float (&a)[4][4], const float* __restrict__ bias) {
    float4 b = *(const float4*)(bias + j4);
#pragma unroll
    for (int aa = 0; aa < 4; ++aa) {
        float* row = Hs + (i4 + aa) * 68 + j4;
        row[0] = gelu_f(a[aa][0] + b.x);
        row[1] = gelu_f(a[aa][1] + b.y);
        row[2] = gelu_f(a[aa][2] + b.z);
        row[3] = gelu_f(a[aa][3] + b.w);
    }
}

// per-row LayerNorm stats over 64 cols of row-major H
__device__ __forceinline__ void ln_stats(const float* __restrict__ Hs, float* __restrict__ st, int tid) {
    if (tid < 64) {
        float s = 0.0f, s2 = 0.0f;
#pragma unroll
        for (int c = 0; c < 16; ++c) {
            float4 v = *(const float4*)(Hs + tid * 68 + 4 * c);
            s += v.x + v.y + v.z + v.w;
            s2 += v.x * v.x + v.y * v.y + v.z * v.z + v.w * v.w;
        }
        float m = s * (1.0f / 64.0f);
        float var = s2 * (1.0f / 64.0f) - m * m;
        st[tid] = m;
        st[64 + tid] = rsqrtf(fmaxf(var, 0.0f) + 1e-5f);
    }
}

__device__ __forceinline__ void red_v4(float* p, float4 v) {
    asm volatile("red.global.add.v4.f32 [%0], {%1,%2,%3,%4};"
                 :: "l"(p), "f"(v.x), "f"(v.y), "f"(v.z), "f"(v.w) : "memory");
}

// ---------------- zero scratch ----------------
__global__ void zero_kernel() {
    int total = Nn * Hdim + Nn + Gg * Hdim + Gg;
    for (int i = blockIdx.x * blockDim.x + threadIdx.x; i < total; i += gridDim.x * blockDim.x) {
        if (i < Nn * Hdim) g_aggsum[i] = 0.0f;
        else if (i < Nn * Hdim + Nn) g_aggcnt[i - Nn * Hdim] = 0.0f;
        else if (i < Nn * Hdim + Nn + Gg * Hdim) g_gsum[i - Nn * Hdim - Nn] = 0.0f;
        else g_gcnt[i - Nn * Hdim - Nn - Gg * Hdim] = 0.0f;
    }
}

// ---------------- kernel 1: fused edge MLP + message MLP + scatter ----------------
#define E_OW1 0
#define E_OW2 16384
#define E_ON1 20480
#define E_ON2 28672
#define E_OB  32768
#define E_OX  33280
#define E_OH  50688
#define E_OST 55040
#define E_OROW 55168
#define E_SMEM_BYTES (55232 * 4)

__global__ __launch_bounds__(256, 1) void edge_node1_kernel(
    const float* __restrict__ x, const int* __restrict__ ei,
    const float* __restrict__ ea, const float* __restrict__ u,
    const int* __restrict__ batch,
    const float* __restrict__ eW1, const float* __restrict__ eb1,
    const float* __restrict__ eW2, const float* __restrict__ eb2,
    const float* __restrict__ egm, const float* __restrict__ ebt,
    const float* __restrict__ nW1, const float* __restrict__ nb1,
    const float* __restrict__ nW2, const float* __restrict__ nb2,
    const float* __restrict__ ngm, const float* __restrict__ nbt,
    float* __restrict__ edge_out) {
    extern __shared__ float sm[];
    int tid = threadIdx.x;
    cp_smem(sm + E_OW1, eW1, 16384, tid);
    cp_smem(sm + E_OW2, eW2, 4096, tid);
    cp_smem(sm + E_ON1, nW1, 8192, tid);
    cp_smem(sm + E_ON2, nW2, 4096, tid);
    if (tid < 64) {
        sm[E_OB + tid] = eb1[tid];       sm[E_OB + 64 + tid] = eb2[tid];
        sm[E_OB + 128 + tid] = egm[tid]; sm[E_OB + 192 + tid] = ebt[tid];
        sm[E_OB + 256 + tid] = nb1[tid]; sm[E_OB + 320 + tid] = nb2[tid];
        sm[E_OB + 384 + tid] = ngm[tid]; sm[E_OB + 448 + tid] = nbt[tid];
    }
    __syncthreads();

    const int i4 = (tid >> 4) << 2;
    const int j4 = (tid & 15) << 2;
    int* srow = (int*)(sm + E_OROW);

    for (int t = blockIdx.x; t < Ee / 64; t += gridDim.x) {
        // -------- gather: [x[row] | x[col] | edge_attr | u[batch[row]]] k-major, swizzled
        {
            int e = tid >> 2, seg = tid & 3;
            int eg_ = t * 64 + e;
            int row = ei[eg_];
            const float* src;
            if (seg == 0) {
                src = x + (size_t)row * 64;
                srow[e] = row;
                atomicAdd(&g_aggcnt[row], 1.0f);
            } else if (seg == 1) {
                int col = ei[Ee + eg_];
                src = x + (size_t)col * 64;
            } else if (seg == 2) {
                src = ea + (size_t)eg_ * 64;
            } else {
                int b = batch[row];
                src = u + (size_t)b * 64;
            }
            int ep = e ^ (seg << 3);
            float* dst = sm + E_OX + seg * 64 * 68 + ep;
            const float4* s4 = (const float4*)src;
#pragma unroll
            for (int tt = 0; tt < 16; ++tt) {
                float4 v = s4[tt];
                float* d = dst + tt * 4 * 68;
                d[0] = v.x; d[68] = v.y; d[136] = v.z; d[204] = v.w;
            }
        }
        __syncthreads();

        float acc[4][4];
        // edge MLP layer 1 (K=256)
        zero4(acc);
        gemmA<256, 0>(sm + E_OX, sm + E_OW1, i4, j4, acc);
        storeH(sm + E_OH, i4, j4, acc, sm + E_OB + 0);
        __syncthreads();
        // edge MLP layer 2 (K=64)
        zero4(acc);
        gemmB<64>(sm + E_OH, sm + E_OW2, i4, j4, acc);
        __syncthreads();
        storeH(sm + E_OH, i4, j4, acc, sm + E_OB + 64);
        __syncthreads();
        ln_stats(sm + E_OH, sm + E_OST, tid);
        __syncthreads();
        // LN -> edge_attr_new: write global + place into sX rows 128..191 (swizzle 16)
        {
            int j = tid & 63, g2 = tid >> 6;
            float gj = sm[E_OB + 128 + j], bj = sm[E_OB + 192 + j];
            float* ebase = edge_out + (size_t)t * 64 * 64;
#pragma unroll
            for (int r = 0; r < 16; ++r) {
                int e = g2 * 16 + r;
                float v = sm[E_OH + e * 68 + j];
                float nv = (v - sm[E_OST + e]) * sm[E_OST + 64 + e] * gj + bj;
                sm[E_OX + (128 + j) * 68 + (e ^ 16)] = nv;
                ebase[(size_t)e * 64 + j] = nv;
            }
        }
        __syncthreads();
        // message MLP layer 1: input = sX rows 64..191 = [x[col] | edge_attr_new] (K=128)
        zero4(acc);
        gemmA<128, 64>(sm + E_OX, sm + E_ON1, i4, j4, acc);
        storeH(sm + E_OH, i4, j4, acc, sm + E_OB + 256);
        __syncthreads();
        // message MLP layer 2 (K=64)
        zero4(acc);
        gemmB<64>(sm + E_OH, sm + E_ON2, i4, j4, acc);
        __syncthreads();
        storeH(sm + E_OH, i4, j4, acc, sm + E_OB + 320);
        __syncthreads();
        ln_stats(sm + E_OH, sm + E_OST, tid);
        __syncthreads();
        // LN + vectorized scatter-add into aggsum[row]
        {
            float4 g4 = *(const float4*)(sm + E_OB + 384 + j4);
            float4 b4 = *(const float4*)(sm + E_OB + 448 + j4);
#pragma unroll
            for (int ebk = 0; ebk < 4; ++ebk) {
                int e = (tid >> 4) + (ebk << 4);
                float mn = sm[E_OST + e], rs = sm[E_OST + 64 + e];
                float4 v = *(const float4*)(sm + E_OH + e * 68 + j4);
                v.x = (v.x - mn) * rs * g4.x + b4.x;
                v.y = (v.y - mn) * rs * g4.y + b4.y;
                v.z = (v.z - mn) * rs * g4.z + b4.z;
                v.w = (v.w - mn) * rs * g4.w + b4.w;
                red_v4(g_aggsum + (size_t)srow[e] * 64 + j4, v);
            }
        }
        __syncthreads();
    }
}

// ---------------- kernel 2: node update MLP + graph scatter ----------------
#define N_OW1 0
#define N_OW2 8192
#define N_OB  12288
#define N_OX  12544
#define N_OH  21248
#define N_OST 25600
#define N_OBI 25728
#define N_SMEM_BYTES (25792 * 4)

__global__ __launch_bounds__(256, 1) void node2_kernel(
    const float* __restrict__ u, const int* __restrict__ batch,
    const float* __restrict__ W1, const float* __restrict__ b1,
    const float* __restrict__ W2, const float* __restrict__ b2,
    const float* __restrict__ gm, const float* __restrict__ bt,
    float* __restrict__ x_out) {
    extern __shared__ float sm[];
    int tid = threadIdx.x;
    cp_smem(sm + N_OW1, W1, 8192, tid);
    cp_smem(sm + N_OW2, W2, 4096, tid);
    if (tid < 64) {
        sm[N_OB + tid] = b1[tid];       sm[N_OB + 64 + tid] = b2[tid];
        sm[N_OB + 128 + tid] = gm[tid]; sm[N_OB + 192 + tid] = bt[tid];
    }
    __syncthreads();
    const int i4 = (tid >> 4) << 2;
    const int j4 = (tid & 15) << 2;
    int* sbi = (int*)(sm + N_OBI);
    const int nTiles = (Nn + 63) / 64;

    for (int t = blockIdx.x; t < nTiles; t += gridDim.x) {
        {
            int e = tid >> 2, q = tid & 3;
            int n = t * 64 + e;
            bool valid = n < Nn;
            int b = valid ? batch[n] : 0;
            if (q == 0) {
                sbi[e] = b;
                if (valid) atomicAdd(&g_gcnt[b], 1.0f);
            }
            float inv = valid ? 1.0f / fmaxf(g_aggcnt[n], 1.0f) : 1.0f;
#pragma unroll
            for (int tt = 0; tt < 8; ++tt) {
                int k0 = q * 32 + tt * 4;
                float4 v = make_float4(0.f, 0.f, 0.f, 0.f);
                if (valid) {
                    if (k0 < 64) {
                        v = ((const float4*)(g_aggsum + (size_t)n * 64))[k0 >> 2];
                        v.x *= inv; v.y *= inv; v.z *= inv; v.w *= inv;
                    } else {
                        v = ((const float4*)(u + (size_t)b * 64))[(k0 - 64) >> 2];
                    }
                }
                int ep = e ^ ((k0 >> 6) << 3);
                float* d = sm + N_OX + k0 * 68 + ep;
                d[0] = v.x; d[68] = v.y; d[136] = v.z; d[204] = v.w;
            }
        }
        __syncthreads();
        float acc[4][4];
        zero4(acc);
        gemmA<128, 0>(sm + N_OX, sm + N_OW1, i4, j4, acc);
        storeH(sm + N_OH, i4, j4, acc, sm + N_OB);
        __syncthreads();
        zero4(acc);
        gemmB<64>(sm + N_OH, sm + N_OW2, i4, j4, acc);
        __syncthreads();
        storeH(sm + N_OH, i4, j4, acc, sm + N_OB + 64);
        __syncthreads();
        ln_stats(sm + N_OH, sm + N_OST, tid);
        __syncthreads();
        {
            int j = tid & 63, g2 = tid >> 6;
            float gj = sm[N_OB + 128 + j], bj = sm[N_OB + 192 + j];
#pragma unroll
            for (int r = 0; r < 16; ++r) {
                int e = g2 * 16 + r;
                int n = t * 64 + e;
                float v = sm[N_OH + e * 68 + j];
                float nv = (v - sm[N_OST + e]) * sm[N_OST + 64 + e] * gj + bj;
                sm[N_OH + e * 68 + j] = nv;  // in-place: same (e,j) owner
                if (n < Nn) x_out[(size_t)n * 64 + j] = nv;
            }
        }
        __syncthreads();
        {
#pragma unroll
            for (int ebk = 0; ebk < 4; ++ebk) {
                int e = (tid >> 4) + (ebk << 4);
                int n = t * 64 + e;
                if (n < Nn) {
                    float4 v = *(const float4*)(sm + N_OH + e * 68 + j4);
                    red_v4(g_gsum + (size_t)sbi[e] * 64 + j4, v);
                }
            }
        }
        __syncthreads();
    }
}

// ---------------- kernel 3: global MLP ----------------
__global__ __launch_bounds__(256, 1) void glob_kernel(
    const float* __restrict__ u,
    const float* __restrict__ W1, const float* __restrict__ b1,
    const float* __restrict__ W2, const float* __restrict__ b2,
    const float* __restrict__ gm, const float* __restrict__ bt,
    float* __restrict__ u_out) {
    extern __shared__ float sm[];
    int tid = threadIdx.x;
    cp_smem(sm + N_OW1, W1, 8192, tid);
    cp_smem(sm + N_OW2, W2, 4096, tid);
    if (tid < 64) {
        sm[N_OB + tid] = b1[tid];       sm[N_OB + 64 + tid] = b2[tid];
        sm[N_OB + 128 + tid] = gm[tid]; sm[N_OB + 192 + tid] = bt[tid];
    }
    __syncthreads();
    const int i4 = (tid >> 4) << 2;
    const int j4 = (tid & 15) << 2;
    {
        int e = tid >> 2, q = tid & 3;
        float inv = 1.0f / fmaxf(g_gcnt[e], 1.0f);
#pragma unroll
        for (int tt = 0; tt < 8; ++tt) {
            int k0 = q * 32 + tt * 4;
            float4 v;
            if (k0 < 64) {
                v = ((const float4*)(u + (size_t)e * 64))[k0 >> 2];
            } else {
                v = ((const float4*)(g_gsum + (size_t)e * 64))[(k0 - 64) >> 2];
                v.x *= inv; v.y *= inv; v.z *= inv; v.w *= inv;
            }
            int ep = e ^ ((k0 >> 6) << 3);
            float* d = sm + N_OX + k0 * 68 + ep;
            d[0] = v.x; d[68] = v.y; d[136] = v.z; d[204] = v.w;
        }
    }
    __syncthreads();
    float acc[4][4];
    zero4(acc);
    gemmA<128, 0>(sm + N_OX, sm + N_OW1, i4, j4, acc);
    storeH(sm + N_OH, i4, j4, acc, sm + N_OB);
    __syncthreads();
    zero4(acc);
    gemmB<64>(sm + N_OH, sm + N_OW2, i4, j4, acc);
    __syncthreads();
    storeH(sm + N_OH, i4, j4, acc, sm + N_OB + 64);
    __syncthreads();
    ln_stats(sm + N_OH, sm + N_OST, tid);
    __syncthreads();
    {
        int j = tid & 63, g2 = tid >> 6;
        float gj = sm[N_OB + 128 + j], bj = sm[N_OB + 192 + j];
#pragma unroll
        for (int r = 0; r < 16; ++r) {
            int e = g2 * 16 + r;
            float v = sm[N_OH + e * 68 + j];
            float nv = (v - sm[N_OST + e]) * sm[N_OST + 64 + e] * gj + bj;
            u_out[(size_t)e * 64 + j] = nv;
        }
    }
}

// ---------------- launch ----------------
extern "C" void kernel_launch(void* const* d_in, const int* in_sizes, int n_in,
                              void* d_out, int out_size) {
    const float* x = (const float*)d_in[0];
    const int* ei = (const int*)d_in[1];
    const float* ea = (const float*)d_in[2];
    const float* u = (const float*)d_in[3];
    const int* batch = (const int*)d_in[4];

    const float* eW1 = (const float*)d_in[5];
    const float* eb1 = (const float*)d_in[6];
    const float* eW2 = (const float*)d_in[7];
    const float* eb2 = (const float*)d_in[8];
    const float* egm = (const float*)d_in[9];
    const float* ebt = (const float*)d_in[10];
    const float* n1W1 = (const float*)d_in[11];
    const float* n1b1 = (const float*)d_in[12];
    const float* n1W2 = (const float*)d_in[13];
    const float* n1b2 = (const float*)d_in[14];
    const float* n1g = (const float*)d_in[15];
    const float* n1bt = (const float*)d_in[16];
    const float* n2W1 = (const float*)d_in[17];
    const float* n2b1 = (const float*)d_in[18];
    const float* n2W2 = (const float*)d_in[19];
    const float* n2b2 = (const float*)d_in[20];
    const float* n2g = (const float*)d_in[21];
    const float* n2bt = (const float*)d_in[22];
    const float* gW1 = (const float*)d_in[23];
    const float* gb1 = (const float*)d_in[24];
    const float* gW2 = (const float*)d_in[25];
    const float* gb2 = (const float*)d_in[26];
    const float* gg = (const float*)d_in[27];
    const float* gbt = (const float*)d_in[28];

    float* out = (float*)d_out;
    float* x_out = out;                               // (N, 64)
    float* e_out = out + (size_t)Nn * 64;             // (E, 64)
    float* u_out = out + (size_t)(Nn + Ee) * 64;      // (G, 64)

    cudaFuncSetAttribute(edge_node1_kernel, cudaFuncAttributeMaxDynamicSharedMemorySize, E_SMEM_BYTES);
    cudaFuncSetAttribute(node2_kernel, cudaFuncAttributeMaxDynamicSharedMemorySize, N_SMEM_BYTES);
    cudaFuncSetAttribute(glob_kernel, cudaFuncAttributeMaxDynamicSharedMemorySize, N_SMEM_BYTES);

    zero_kernel<<<2048, 256>>>();
    edge_node1_kernel<<<1184, 256, E_SMEM_BYTES>>>(
        x, ei, ea, u, batch,
        eW1, eb1, eW2, eb2, egm, ebt,
        n1W1, n1b1, n1W2, n1b2, n1g, n1bt,
        e_out);
    node2_kernel<<<1563, 256, N_SMEM_BYTES>>>(
        u, batch, n2W1, n2b1, n2W2, n2b2, n2g, n2bt, x_out);
    glob_kernel<<<1, 256, N_SMEM_BYTES>>>(
        u, gW1, gb1, gW2, gb2, gg, gbt, u_out);
}

// round 5
// speedup vs baseline: 1.0912x; 1.0912x over previous
#include <cuda_runtime.h>

#define Hdim 64
#define Nn   100000
#define Ee   1000000
#define Gg   64

typedef unsigned long long u64;

// ---------------- scratch (static device arrays: no allocation) ----------------
__device__ float g_aggsum[Nn * Hdim];
__device__ float g_aggcnt[Nn];
__device__ float g_gsum[Gg * Hdim];
__device__ float g_gcnt[Gg];

// ---------------- packed f32x2 helpers ----------------
__device__ __forceinline__ u64 bcast2(float x) {
    u64 r; unsigned xi = __float_as_uint(x);
    asm("mov.b64 %0, {%1, %2};" : "=l"(r) : "r"(xi), "r"(xi));
    return r;
}
__device__ __forceinline__ void ffma2(u64& d, u64 a, u64 b) {
    asm("fma.rn.f32x2 %0, %1, %2, %0;" : "+l"(d) : "l"(a), "l"(b));
}
__device__ __forceinline__ float2 unpack2(u64 v) {
    unsigned lo, hi;
    asm("mov.b64 {%0, %1}, %2;" : "=r"(lo), "=r"(hi) : "l"(v));
    return make_float2(__uint_as_float(lo), __uint_as_float(hi));
}
__device__ __forceinline__ float fsel(float4 v, int i) {
    return i == 0 ? v.x : (i == 1 ? v.y : (i == 2 ? v.z : v.w));
}

// ---------------- helpers ----------------
__device__ __forceinline__ float gelu_f(float v) {
    return 0.5f * v * (1.0f + erff(v * 0.7071067811865476f));
}

__device__ __forceinline__ void zero8(u64 (&a)[4][2]) {
#pragma unroll
    for (int i = 0; i < 4; ++i) { a[i][0] = 0ULL; a[i][1] = 0ULL; }
}

__device__ __forceinline__ void cp_smem(float* dst, const float* src, int nfloats, int tid) {
    const float4* s4 = (const float4*)src;
    float4* d4 = (float4*)dst;
    for (int i = tid; i < (nfloats >> 2); i += 256) d4[i] = s4[i];
}

// type-A GEMM (packed j): X k-major in smem, stride 68, e-index XOR-swizzled
template <int K, int KB>
__device__ __forceinline__ void gemmA2(const float* __restrict__ Xs, const float* __restrict__ Ws,
                                       int i4, int j4, u64 (&a)[4][2]) {
#pragma unroll 4
    for (int k = 0; k < K; ++k) {
        int kk = KB + k;
        float4 xv = *(const float4*)(Xs + kk * 68 + (i4 ^ (((kk >> 6) & 3) << 3)));
        ulonglong2 wv = *(const ulonglong2*)(Ws + k * 64 + j4);
        u64 x0 = bcast2(xv.x), x1 = bcast2(xv.y), x2 = bcast2(xv.z), x3 = bcast2(xv.w);
        ffma2(a[0][0], x0, wv.x); ffma2(a[0][1], x0, wv.y);
        ffma2(a[1][0], x1, wv.x); ffma2(a[1][1], x1, wv.y);
        ffma2(a[2][0], x2, wv.x); ffma2(a[2][1], x2, wv.y);
        ffma2(a[3][0], x3, wv.x); ffma2(a[3][1], x3, wv.y);
    }
}

// type-B GEMM (packed j): H row-major in smem (stride 68), float4 loads along k
template <int K>
__device__ __forceinline__ void gemmB2(const float* __restrict__ Hs, const float* __restrict__ Ws,
                                       int i4, int j4, u64 (&a)[4][2]) {
#pragma unroll 2
    for (int k0 = 0; k0 < K; k0 += 4) {
        float4 h0 = *(const float4*)(Hs + (i4 + 0) * 68 + k0);
        float4 h1 = *(const float4*)(Hs + (i4 + 1) * 68 + k0);
        float4 h2 = *(const float4*)(Hs + (i4 + 2) * 68 + k0);
        float4 h3 = *(const float4*)(Hs + (i4 + 3) * 68 + k0);
#pragma unroll
        for (int dk = 0; dk < 4; ++dk) {
            ulonglong2 wv = *(const ulonglong2*)(Ws + (k0 + dk) * 64 + j4);
            u64 x0 = bcast2(fsel(h0, dk));
            u64 x1 = bcast2(fsel(h1, dk));
            u64 x2 = bcast2(fsel(h2, dk));
            u64 x3 = bcast2(fsel(h3, dk));
            ffma2(a[0][0], x0, wv.x); ffma2(a[0][1], x0, wv.y);
            ffma2(a[1][0], x1, wv.x); ffma2(a[1][1], x1, wv.y);
            ffma2(a[2][0], x2, wv.x); ffma2(a[2][1], x2, wv.y);
            ffma2(a[3][0], x3, wv.x); ffma2(a[3][1], x3, wv.y);
        }
    }
}

// bias + exact GELU, store row-major into H (stride 68)
__device__ __forceinline__ void storeH2(float* __restrict__ Hs, int i4, int j4,
                                        u64 (&a)[4][2], const float* __restrict__ bias) {
    float4 b = *(const float4*)(bias + j4);
#pragma unroll
    for (int aa = 0; aa < 4; ++aa) {
        float2 p0 = unpack2(a[aa][0]);
        float2 p1 = unpack2(a[aa][1]);
        float* row = Hs + (i4 + aa) * 68 + j4;
        row[0] = gelu_f(p0.x + b.x);
        row[1] = gelu_f(p0.y + b.y);
        row[2] = gelu_f(p1.x + b.z);
        row[3] = gelu_f(p1.y + b.w);
    }
}

// per-row LayerNorm stats over 64 cols of row-major H
__device__ __forceinline__ void ln_stats(const float* __restrict__ Hs, float* __restrict__ st, int tid) {
    if (tid < 64) {
        float s = 0.0f, s2 = 0.0f;
#pragma unroll
        for (int c = 0; c < 16; ++c) {
            float4 v = *(const float4*)(Hs + tid * 68 + 4 * c);
            s += v.x + v.y + v.z + v.w;
            s2 += v.x * v.x + v.y * v.y + v.z * v.z + v.w * v.w;
        }
        float m = s * (1.0f / 64.0f);
        float var = s2 * (1.0f / 64.0f) - m * m;
        st[tid] = m;
        st[64 + tid] = rsqrtf(fmaxf(var, 0.0f) + 1e-5f);
    }
}

__device__ __forceinline__ void red_v4(float* p, float4 v) {
    asm volatile("red.global.add.v4.f32 [%0], {%1,%2,%3,%4};"
                 :: "l"(p), "f"(v.x), "f"(v.y), "f"(v.z), "f"(v.w) : "memory");
}

// ---------------- zero scratch ----------------
__global__ void zero_kernel() {
    int total = Nn * Hdim + Nn + Gg * Hdim + Gg;
    for (int i = blockIdx.x * blockDim.x + threadIdx.x; i < total; i += gridDim.x * blockDim.x) {
        if (i < Nn * Hdim) g_aggsum[i] = 0.0f;
        else if (i < Nn * Hdim + Nn) g_aggcnt[i - Nn * Hdim] = 0.0f;
        else if (i < Nn * Hdim + Nn + Gg * Hdim) g_gsum[i - Nn * Hdim - Nn] = 0.0f;
        else g_gcnt[i - Nn * Hdim - Nn - Gg * Hdim] = 0.0f;
    }
}

// ---------------- kernel 1: fused edge MLP + message MLP + scatter ----------------
#define E_OW1 0
#define E_OW2 16384
#define E_ON1 20480
#define E_ON2 28672
#define E_OB  32768
#define E_OX  33280
#define E_OH  50688
#define E_OST 55040
#define E_OROW 55168
#define E_SMEM_BYTES (55232 * 4)

__global__ __launch_bounds__(256, 1) void edge_node1_kernel(
    const float* __restrict__ x, const int* __restrict__ ei,
    const float* __restrict__ ea, const float* __restrict__ u,
    const int* __restrict__ batch,
    const float* __restrict__ eW1, const float* __restrict__ eb1,
    const float* __restrict__ eW2, const float* __restrict__ eb2,
    const float* __restrict__ egm, const float* __restrict__ ebt,
    const float* __restrict__ nW1, const float* __restrict__ nb1,
    const float* __restrict__ nW2, const float* __restrict__ nb2,
    const float* __restrict__ ngm, const float* __restrict__ nbt,
    float* __restrict__ edge_out) {
    extern __shared__ float sm[];
    int tid = threadIdx.x;
    cp_smem(sm + E_OW1, eW1, 16384, tid);
    cp_smem(sm + E_OW2, eW2, 4096, tid);
    cp_smem(sm + E_ON1, nW1, 8192, tid);
    cp_smem(sm + E_ON2, nW2, 4096, tid);
    if (tid < 64) {
        sm[E_OB + tid] = eb1[tid];       sm[E_OB + 64 + tid] = eb2[tid];
        sm[E_OB + 128 + tid] = egm[tid]; sm[E_OB + 192 + tid] = ebt[tid];
        sm[E_OB + 256 + tid] = nb1[tid]; sm[E_OB + 320 + tid] = nb2[tid];
        sm[E_OB + 384 + tid] = ngm[tid]; sm[E_OB + 448 + tid] = nbt[tid];
    }
    __syncthreads();

    const int i4 = (tid >> 4) << 2;
    const int j4 = (tid & 15) << 2;
    int* srow = (int*)(sm + E_OROW);

    for (int t = blockIdx.x; t < Ee / 64; t += gridDim.x) {
        // -------- gather: [x[row] | x[col] | edge_attr | u[batch[row]]] k-major, swizzled
        {
            int e = tid >> 2, seg = tid & 3;
            int eg_ = t * 64 + e;
            int row = ei[eg_];
            const float* src;
            if (seg == 0) {
                src = x + (size_t)row * 64;
                srow[e] = row;
                atomicAdd(&g_aggcnt[row], 1.0f);
            } else if (seg == 1) {
                int col = ei[Ee + eg_];
                src = x + (size_t)col * 64;
            } else if (seg == 2) {
                src = ea + (size_t)eg_ * 64;
            } else {
                int b = batch[row];
                src = u + (size_t)b * 64;
            }
            int ep = e ^ (seg << 3);
            float* dst = sm + E_OX + seg * 64 * 68 + ep;
            const float4* s4 = (const float4*)src;
#pragma unroll
            for (int tt = 0; tt < 16; ++tt) {
                float4 v = s4[tt];
                float* d = dst + tt * 4 * 68;
                d[0] = v.x; d[68] = v.y; d[136] = v.z; d[204] = v.w;
            }
        }
        __syncthreads();

        u64 acc[4][2];
        // edge MLP layer 1 (K=256)
        zero8(acc);
        gemmA2<256, 0>(sm + E_OX, sm + E_OW1, i4, j4, acc);
        storeH2(sm + E_OH, i4, j4, acc, sm + E_OB + 0);
        __syncthreads();
        // edge MLP layer 2 (K=64)
        zero8(acc);
        gemmB2<64>(sm + E_OH, sm + E_OW2, i4, j4, acc);
        __syncthreads();
        storeH2(sm + E_OH, i4, j4, acc, sm + E_OB + 64);
        __syncthreads();
        ln_stats(sm + E_OH, sm + E_OST, tid);
        __syncthreads();
        // LN -> edge_attr_new: write global + place into sX rows 128..191 (swizzle 16)
        {
            int j = tid & 63, g2 = tid >> 6;
            float gj = sm[E_OB + 128 + j], bj = sm[E_OB + 192 + j];
            float* ebase = edge_out + (size_t)t * 64 * 64;
#pragma unroll
            for (int r = 0; r < 16; ++r) {
                int e = g2 * 16 + r;
                float v = sm[E_OH + e * 68 + j];
                float nv = (v - sm[E_OST + e]) * sm[E_OST + 64 + e] * gj + bj;
                sm[E_OX + (128 + j) * 68 + (e ^ 16)] = nv;
                ebase[(size_t)e * 64 + j] = nv;
            }
        }
        __syncthreads();
        // message MLP layer 1: input = sX rows 64..191 = [x[col] | edge_attr_new] (K=128)
        zero8(acc);
        gemmA2<128, 64>(sm + E_OX, sm + E_ON1, i4, j4, acc);
        storeH2(sm + E_OH, i4, j4, acc, sm + E_OB + 256);
        __syncthreads();
        // message MLP layer 2 (K=64)
        zero8(acc);
        gemmB2<64>(sm + E_OH, sm + E_ON2, i4, j4, acc);
        __syncthreads();
        storeH2(sm + E_OH, i4, j4, acc, sm + E_OB + 320);
        __syncthreads();
        ln_stats(sm + E_OH, sm + E_OST, tid);
        __syncthreads();
        // LN + vectorized scatter-add into aggsum[row]
        {
            float4 g4 = *(const float4*)(sm + E_OB + 384 + j4);
            float4 b4 = *(const float4*)(sm + E_OB + 448 + j4);
#pragma unroll
            for (int ebk = 0; ebk < 4; ++ebk) {
                int e = (tid >> 4) + (ebk << 4);
                float mn = sm[E_OST + e], rs = sm[E_OST + 64 + e];
                float4 v = *(const float4*)(sm + E_OH + e * 68 + j4);
                v.x = (v.x - mn) * rs * g4.x + b4.x;
                v.y = (v.y - mn) * rs * g4.y + b4.y;
                v.z = (v.z - mn) * rs * g4.z + b4.z;
                v.w = (v.w - mn) * rs * g4.w + b4.w;
                red_v4(g_aggsum + (size_t)srow[e] * 64 + j4, v);
            }
        }
        __syncthreads();
    }
}

// ---------------- kernel 2: node update MLP + graph scatter ----------------
#define N_OW1 0
#define N_OW2 8192
#define N_OB  12288
#define N_OX  12544
#define N_OH  21248
#define N_OST 25600
#define N_OBI 25728
#define N_SMEM_BYTES (25792 * 4)

__global__ __launch_bounds__(256, 1) void node2_kernel(
    const float* __restrict__ u, const int* __restrict__ batch,
    const float* __restrict__ W1, const float* __restrict__ b1,
    const float* __restrict__ W2, const float* __restrict__ b2,
    const float* __restrict__ gm, const float* __restrict__ bt,
    float* __restrict__ x_out) {
    extern __shared__ float sm[];
    int tid = threadIdx.x;
    cp_smem(sm + N_OW1, W1, 8192, tid);
    cp_smem(sm + N_OW2, W2, 4096, tid);
    if (tid < 64) {
        sm[N_OB + tid] = b1[tid];       sm[N_OB + 64 + tid] = b2[tid];
        sm[N_OB + 128 + tid] = gm[tid]; sm[N_OB + 192 + tid] = bt[tid];
    }
    __syncthreads();
    const int i4 = (tid >> 4) << 2;
    const int j4 = (tid & 15) << 2;
    int* sbi = (int*)(sm + N_OBI);
    const int nTiles = (Nn + 63) / 64;

    for (int t = blockIdx.x; t < nTiles; t += gridDim.x) {
        {
            int e = tid >> 2, q = tid & 3;
            int n = t * 64 + e;
            bool valid = n < Nn;
            int b = valid ? batch[n] : 0;
            if (q == 0) {
                sbi[e] = b;
                if (valid) atomicAdd(&g_gcnt[b], 1.0f);
            }
            float inv = valid ? 1.0f / fmaxf(g_aggcnt[n], 1.0f) : 1.0f;
#pragma unroll
            for (int tt = 0; tt < 8; ++tt) {
                int k0 = q * 32 + tt * 4;
                float4 v = make_float4(0.f, 0.f, 0.f, 0.f);
                if (valid) {
                    if (k0 < 64) {
                        v = ((const float4*)(g_aggsum + (size_t)n * 64))[k0 >> 2];
                        v.x *= inv; v.y *= inv; v.z *= inv; v.w *= inv;
                    } else {
                        v = ((const float4*)(u + (size_t)b * 64))[(k0 - 64) >> 2];
                    }
                }
                int ep = e ^ ((k0 >> 6) << 3);
                float* d = sm + N_OX + k0 * 68 + ep;
                d[0] = v.x; d[68] = v.y; d[136] = v.z; d[204] = v.w;
            }
        }
        __syncthreads();
        u64 acc[4][2];
        zero8(acc);
        gemmA2<128, 0>(sm + N_OX, sm + N_OW1, i4, j4, acc);
        storeH2(sm + N_OH, i4, j4, acc, sm + N_OB);
        __syncthreads();
        zero8(acc);
        gemmB2<64>(sm + N_OH, sm + N_OW2, i4, j4, acc);
        __syncthreads();
        storeH2(sm + N_OH, i4, j4, acc, sm + N_OB + 64);
        __syncthreads();
        ln_stats(sm + N_OH, sm + N_OST, tid);
        __syncthreads();
        {
            int j = tid & 63, g2 = tid >> 6;
            float gj = sm[N_OB + 128 + j], bj = sm[N_OB + 192 + j];
#pragma unroll
            for (int r = 0; r < 16; ++r) {
                int e = g2 * 16 + r;
                int n = t * 64 + e;
                float v = sm[N_OH + e * 68 + j];
                float nv = (v - sm[N_OST + e]) * sm[N_OST + 64 + e] * gj + bj;
                sm[N_OH + e * 68 + j] = nv;  // in-place: same (e,j) owner
                if (n < Nn) x_out[(size_t)n * 64 + j] = nv;
            }
        }
        __syncthreads();
        {
#pragma unroll
            for (int ebk = 0; ebk < 4; ++ebk) {
                int e = (tid >> 4) + (ebk << 4);
                int n = t * 64 + e;
                if (n < Nn) {
                    float4 v = *(const float4*)(sm + N_OH + e * 68 + j4);
                    red_v4(g_gsum + (size_t)sbi[e] * 64 + j4, v);
                }
            }
        }
        __syncthreads();
    }
}

// ---------------- kernel 3: global MLP ----------------
__global__ __launch_bounds__(256, 1) void glob_kernel(
    const float* __restrict__ u,
    const float* __restrict__ W1, const float* __restrict__ b1,
    const float* __restrict__ W2, const float* __restrict__ b2,
    const float* __restrict__ gm, const float* __restrict__ bt,
    float* __restrict__ u_out) {
    extern __shared__ float sm[];
    int tid = threadIdx.x;
    cp_smem(sm + N_OW1, W1, 8192, tid);
    cp_smem(sm + N_OW2, W2, 4096, tid);
    if (tid < 64) {
        sm[N_OB + tid] = b1[tid];       sm[N_OB + 64 + tid] = b2[tid];
        sm[N_OB + 128 + tid] = gm[tid]; sm[N_OB + 192 + tid] = bt[tid];
    }
    __syncthreads();
    const int i4 = (tid >> 4) << 2;
    const int j4 = (tid & 15) << 2;
    {
        int e = tid >> 2, q = tid & 3;
        float inv = 1.0f / fmaxf(g_gcnt[e], 1.0f);
#pragma unroll
        for (int tt = 0; tt < 8; ++tt) {
            int k0 = q * 32 + tt * 4;
            float4 v;
            if (k0 < 64) {
                v = ((const float4*)(u + (size_t)e * 64))[k0 >> 2];
            } else {
                v = ((const float4*)(g_gsum + (size_t)e * 64))[(k0 - 64) >> 2];
                v.x *= inv; v.y *= inv; v.z *= inv; v.w *= inv;
            }
            int ep = e ^ ((k0 >> 6) << 3);
            float* d = sm + N_OX + k0 * 68 + ep;
            d[0] = v.x; d[68] = v.y; d[136] = v.z; d[204] = v.w;
        }
    }
    __syncthreads();
    u64 acc[4][2];
    zero8(acc);
    gemmA2<128, 0>(sm + N_OX, sm + N_OW1, i4, j4, acc);
    storeH2(sm + N_OH, i4, j4, acc, sm + N_OB);
    __syncthreads();
    zero8(acc);
    gemmB2<64>(sm + N_OH, sm + N_OW2, i4, j4, acc);
    __syncthreads();
    storeH2(sm + N_OH, i4, j4, acc, sm + N_OB + 64);
    __syncthreads();
    ln_stats(sm + N_OH, sm + N_OST, tid);
    __syncthreads();
    {
        int j = tid & 63, g2 = tid >> 6;
        float gj = sm[N_OB + 128 + j], bj = sm[N_OB + 192 + j];
#pragma unroll
        for (int r = 0; r < 16; ++r) {
            int e = g2 * 16 + r;
            float v = sm[N_OH + e * 68 + j];
            float nv = (v - sm[N_OST + e]) * sm[N_OST + 64 + e] * gj + bj;
            u_out[(size_t)e * 64 + j] = nv;
        }
    }
}

// ---------------- launch ----------------
extern "C" void kernel_launch(void* const* d_in, const int* in_sizes, int n_in,
                              void* d_out, int out_size) {
    const float* x = (const float*)d_in[0];
    const int* ei = (const int*)d_in[1];
    const float* ea = (const float*)d_in[2];
    const float* u = (const float*)d_in[3];
    const int* batch = (const int*)d_in[4];

    const float* eW1 = (const float*)d_in[5];
    const float* eb1 = (const float*)d_in[6];
    const float* eW2 = (const float*)d_in[7];
    const float* eb2 = (const float*)d_in[8];
    const float* egm = (const float*)d_in[9];
    const float* ebt = (const float*)d_in[10];
    const float* n1W1 = (const float*)d_in[11];
    const float* n1b1 = (const float*)d_in[12];
    const float* n1W2 = (const float*)d_in[13];
    const float* n1b2 = (const float*)d_in[14];
    const float* n1g = (const float*)d_in[15];
    const float* n1bt = (const float*)d_in[16];
    const float* n2W1 = (const float*)d_in[17];
    const float* n2b1 = (const float*)d_in[18];
    const float* n2W2 = (const float*)d_in[19];
    const float* n2b2 = (const float*)d_in[20];
    const float* n2g = (const float*)d_in[21];
    const float* n2bt = (const float*)d_in[22];
    const float* gW1 = (const float*)d_in[23];
    const float* gb1 = (const float*)d_in[24];
    const float* gW2 = (const float*)d_in[25];
    const float* gb2 = (const float*)d_in[26];
    const float* gg = (const float*)d_in[27];
    const float* gbt = (const float*)d_in[28];

    float* out = (float*)d_out;
    float* x_out = out;                               // (N, 64)
    float* e_out = out + (size_t)Nn * 64;             // (E, 64)
    float* u_out = out + (size_t)(Nn + Ee) * 64;      // (G, 64)

    cudaFuncSetAttribute(edge_node1_kernel, cudaFuncAttributeMaxDynamicSharedMemorySize, E_SMEM_BYTES);
    cudaFuncSetAttribute(node2_kernel, cudaFuncAttributeMaxDynamicSharedMemorySize, N_SMEM_BYTES);
    cudaFuncSetAttribute(glob_kernel, cudaFuncAttributeMaxDynamicSharedMemorySize, N_SMEM_BYTES);

    zero_kernel<<<2048, 256>>>();
    edge_node1_kernel<<<1184, 256, E_SMEM_BYTES>>>(
        x, ei, ea, u, batch,
        eW1, eb1, eW2, eb2, egm, ebt,
        n1W1, n1b1, n1W2, n1b2, n1g, n1bt,
        e_out);
    node2_kernel<<<1563, 256, N_SMEM_BYTES>>>(
        u, batch, n2W1, n2b1, n2W2, n2b2, n2g, n2bt, x_out);
    glob_kernel<<<1, 256, N_SMEM_BYTES>>>(
        u, gW1, gb1, gW2, gb2, gg, gbt, u_out);
}